// round 11
// baseline (speedup 1.0000x reference)
#include <cuda_runtime.h>
#include <cuda_bf16.h>
#include <cfloat>
#include <cstdint>

// ---------------------------------------------------------------------------
// RetinaNet postprocess, round 11: ONE persistent kernel, software grid
// barriers (grid sized by occupancy API => all blocks co-resident).
// Phases (direct ports of the round-10 kernels):
//   1 prep   : class-max (SMEM atomicMax) + decode + slab emit (score>CUTOFF)
//   2 rank   : comparison rank of slab keys -> sorted compact arrays
//   3 pair   : upper-triangular pairwise IoU mask rows (64 blocks)
//   4 scan   : block0/warp0 exact greedy, cp.async SMEM ring prefetch,
//              owning-lane chunk simulation (no votes), early-exit at 300
//   5 flag   : tail vs snapshot kept set (skipped when nk==300)
//   6 tail   : block0 serial reference greedy over survivors (normally none)
//   7 final  : warp-per-keep class argmax + output tuple
// Exactness: unchanged from round 10 (clean score cut + monotone kept set +
// exact ordered tail; overflow => slab empty => exact-but-slow tail path).
// ---------------------------------------------------------------------------

#define MAXA   262144
#define MAXDET 300
#define T0     2048
#define W0     32
#define NCH    8
#define BLK    256
#define PSTTHD 0.05f
#define CUTOFF 0.99990f
#define NMSTHD 0.5f

typedef unsigned long long ull;

__device__ float  g_keys [MAXA];
__device__ float4 g_boxes[MAXA];
__device__ float  g_areas[MAXA];
__device__ ull    g_ckeys[T0];
__device__ int    g_cidx [T0];
__device__ float4 g_cbox [T0];
__device__ float  g_carea[T0];
__device__ ull    g_mask [T0 * W0];
__device__ ull    g_skey [MAXA];
__device__ float4 g_kbox [MAXDET];
__device__ float  g_karea[MAXDET];
__device__ int    g_keep [MAXDET];
__device__ int    g_scnt;
__device__ int    g_nsurv;
__device__ int    g_nk;
__device__ int    g_overflow;
__device__ unsigned g_barcnt;
__device__ unsigned g_done;

struct SMem {
    union {
        unsigned srow[64];                                    // prep
        ull skeys[T0];                                        // rank (16 KB)
        struct { float4 scb[T0]; float sca[T0]; } p;          // pair (40 KB)
        struct { ull ring[NCH][16][32]; int spos[MAXDET]; } s;// scan (33 KB)
        struct { float4 skb[MAXDET]; float ska[MAXDET];       // flag/tail
                 ull sb[BLK]; float4 swin; float swar; } f;
    } u;
};

__device__ __forceinline__ bool sup_test(float x1, float y1, float x2, float y2, float ar,
                                         float X1, float Y1, float X2, float Y2, float AR)
{
    float xx1 = fmaxf(x1, X1);
    float yy1 = fmaxf(y1, Y1);
    float xx2 = fminf(x2, X2);
    float yy2 = fminf(y2, Y2);
    float inter = fmaxf(xx2 - xx1, 0.0f) * fmaxf(yy2 - yy1, 0.0f);
    float iou = inter / (ar + AR - inter + 1e-8f);
    return iou > NMSTHD;
}

__device__ __forceinline__ void grid_barrier(unsigned G, unsigned idx)
{
    __syncthreads();
    if (threadIdx.x == 0) {
        __threadfence();
        atomicAdd(&g_barcnt, 1u);
        unsigned target = idx * G;
        while (*((volatile unsigned*)&g_barcnt) < target) { }
        __threadfence();
    }
    __syncthreads();
}

__device__ __forceinline__ void cpa8(void* dst, const void* src)
{
    unsigned s = (unsigned)__cvta_generic_to_shared(dst);
    asm volatile("cp.async.ca.shared.global [%0], [%1], 8;" :: "r"(s), "l"(src) : "memory");
}
#define CPA_COMMIT()  asm volatile("cp.async.commit_group;" ::: "memory")
#define CPA_WAIT7()   asm volatile("cp.async.wait_group 7;" ::: "memory")
#define CPA_WAITALL() asm volatile("cp.async.wait_all;" ::: "memory")

// ---------------------------------------------------------------------------
__global__ void __launch_bounds__(BLK)
mega_kernel(const float* __restrict__ cls,
            const float* __restrict__ reg,
            const float* __restrict__ anc,
            const int*   __restrict__ ph,
            const int*   __restrict__ pw,
            int A, int C, float* __restrict__ out, unsigned G)
{
    __shared__ SMem sm;
    int t    = threadIdx.x;
    int bid  = blockIdx.x;
    int lane = t & 31;
    int wrp  = t >> 5;

    // ================= Phase 1: prep =================
    int ntiles = (A + 63) / 64;
    for (int tile = bid; tile < ntiles; tile += (int)G) {
        int base = tile * 64;
        if (t < 64) sm.u.srow[t] = 0u;
        __syncthreads();

        if ((C & 3) == 0) {
            int f4r = C >> 2;
            int tot = 64 * f4r;
            const float4* cb = (const float4*)cls + (size_t)base * f4r;
            for (int i = t; i < tot; i += BLK) {
                int r = i / f4r;
                if (base + r < A) {
                    float4 v = cb[i];
                    float m = fmaxf(fmaxf(v.x, v.y), fmaxf(v.z, v.w));
                    atomicMax(&sm.u.srow[r], __float_as_uint(m));
                }
            }
        } else {
            for (int i = t; i < 64 * C; i += BLK) {
                int r = i / C;
                if (base + r < A) {
                    float m = cls[(size_t)(base + r) * C + (i % C)];
                    atomicMax(&sm.u.srow[r], __float_as_uint(m));
                }
            }
        }
        __syncthreads();

        if (t < 64 && base + t < A) {
            int a = base + t;
            float m = __uint_as_float(sm.u.srow[t]);
            g_keys[a] = (m > PSTTHD) ? m : 0.0f;
            if (m > CUTOFF) {
                int p = atomicAdd(&g_scnt, 1);
                if (p < T0)
                    g_ckeys[p] = ((ull)__float_as_uint(m) << 18) |
                                 (ull)(0x3FFFFu - (unsigned)a);
            }
            float4 an = ((const float4*)anc)[a];
            float4 rg = ((const float4*)reg)[a];
            float bw = an.z - an.x;
            float bh = an.w - an.y;
            float cx = an.x + 0.5f * bw;
            float cy = an.y + 0.5f * bh;
            float pcx = cx + (rg.x * 0.1f) * bw;
            float pcy = cy + (rg.y * 0.1f) * bh;
            float pw_ = expf(rg.z * 0.2f) * bw;
            float ph_ = expf(rg.w * 0.2f) * bh;
            float Wd = pw ? (float)__ldg(pw) : 1024.0f;
            float Hd = ph ? (float)__ldg(ph) : 1024.0f;
            float x1 = fmaxf(pcx - 0.5f * pw_, 0.0f);
            float y1 = fmaxf(pcy - 0.5f * ph_, 0.0f);
            float x2 = fminf(pcx + 0.5f * pw_, Wd);
            float y2 = fminf(pcy + 0.5f * ph_, Hd);
            g_boxes[a] = make_float4(x1, y1, x2, y2);
            g_areas[a] = (x2 - x1) * (y2 - y1);
        }
        __syncthreads();
    }
    grid_barrier(G, 1);

    // ================= Phase 2: rank =================
    int scnt = g_scnt;
    int overflow = (scnt > T0) ? 1 : 0;
    int n = overflow ? 0 : scnt;

    int nbr = (n + BLK - 1) / BLK;
    if (bid < nbr) {
        for (int i = t; i < n; i += BLK) sm.u.skeys[i] = g_ckeys[i];
        __syncthreads();
        int i = bid * BLK + t;
        if (i < n) {
            ull mykey = sm.u.skeys[i];
            int r = 0;
            #pragma unroll 4
            for (int j = 0; j < n; j++) r += (sm.u.skeys[j] > mykey) ? 1 : 0;
            int a = (int)(0x3FFFFu - (unsigned)(mykey & 0x3FFFFULL));
            g_cidx[r]  = a;
            g_cbox[r]  = g_boxes[a];
            g_carea[r] = g_areas[a];
        }
    }
    grid_barrier(G, 2);

    // ================= Phase 3: pair =================
    int PB = min((int)G, 64);
    if (bid < PB && n > 0) {
        for (int i = t; i < n; i += BLK) {
            sm.u.p.scb[i] = g_cbox[i];
            sm.u.p.sca[i] = g_carea[i];
        }
        __syncthreads();
        int items = n * W0;
        for (int it = bid * BLK + t; it < items; it += PB * BLK) {
            int i = it >> 5;
            int w = it & 31;
            int jbase = w << 6;
            int jstart = max(jbase, i + 1);
            int jend   = min(jbase + 64, n);
            ull word = 0ULL;
            if (jstart < jend) {
                float4 bi = sm.u.p.scb[i];
                float  ai = sm.u.p.sca[i];
                for (int j = jstart; j < jend; j++) {
                    float4 bj = sm.u.p.scb[j];
                    if (sup_test(bi.x, bi.y, bi.z, bi.w, ai,
                                 bj.x, bj.y, bj.z, bj.w, sm.u.p.sca[j]))
                        word |= 1ULL << (j - jbase);
                }
            }
            g_mask[it] = word;
        }
    }
    grid_barrier(G, 3);

    // ================= Phase 4: scan (block0 / warp0) =================
    if (bid == 0 && wrp == 0) {
        int nchunks = (n + 15) >> 4;
        for (int c = 0; c < NCH; c++) {
            int base = c << 4;
            #pragma unroll
            for (int r = 0; r < 16; r++) {
                int i = base + r;
                if (i < n) cpa8(&sm.u.s.ring[c][r][lane], &g_mask[(size_t)i * W0 + lane]);
            }
            CPA_COMMIT();
        }
        ull removed = 0ULL;
        int nk = 0;
        for (int c = 0; c < nchunks && nk < MAXDET; c++) {
            CPA_WAIT7();
            __syncwarp();
            int slot = c & (NCH - 1);
            int base = c << 4;
            ull buf[16];
            #pragma unroll
            for (int r = 0; r < 16; r++) buf[r] = sm.u.s.ring[slot][r][lane];

            int lim = min(16, n - base);
            int widx = base >> 6;
            ull dec = 0ULL;
            if (lane == widx) {
                ull w = removed;
                for (int r = 0; r < lim; r++) {
                    int bit = (base + r) & 63;
                    if (!((w >> bit) & 1ULL)) {
                        dec |= 1ULL << r;
                        w |= buf[r];
                    }
                }
                removed = w;
            }
            dec = __shfl_sync(0xffffffffu, dec, widx);
            while (dec) {
                int r = __ffsll(dec) - 1;
                dec &= dec - 1;
                removed |= buf[r];
                if (lane == 0) sm.u.s.spos[nk] = base + r;
                nk++;
                if (nk >= MAXDET) break;
            }

            int pbase = (c + NCH) << 4;
            #pragma unroll
            for (int r = 0; r < 16; r++) {
                int i = pbase + r;
                if (i < n) cpa8(&sm.u.s.ring[slot][r][lane], &g_mask[(size_t)i * W0 + lane]);
            }
            CPA_COMMIT();
        }
        CPA_WAITALL();                       // smem reused next phase
        __syncwarp();
        for (int k = lane; k < nk; k += 32) {
            int p = sm.u.s.spos[k];
            g_keep[k]  = g_cidx[p];
            g_kbox[k]  = g_cbox[p];
            g_karea[k] = g_carea[p];
        }
        if (lane == 0) {
            g_nk = nk;
            g_overflow = overflow;
            g_scnt = 0;                      // ready for next replay
            g_nsurv = 0;
        }
    }
    grid_barrier(G, 4);

    // ================= Phase 5: flag =================
    int nk = g_nk;
    if (nk < MAXDET) {
        for (int k = t; k < nk; k += BLK) {
            sm.u.f.skb[k] = g_kbox[k];
            sm.u.f.ska[k] = g_karea[k];
        }
        __syncthreads();
        int sovf = g_overflow;
        for (int a = bid * BLK + t; a < A; a += (int)G * BLK) {
            float key = g_keys[a];
            if (!(key > PSTTHD)) continue;
            if (!sovf && key > CUTOFF) continue;
            float4 b = g_boxes[a];
            float ar = g_areas[a];
            bool sup = false;
            for (int k = 0; k < nk; k++) {
                if (sup_test(b.x, b.y, b.z, b.w, ar,
                             sm.u.f.skb[k].x, sm.u.f.skb[k].y,
                             sm.u.f.skb[k].z, sm.u.f.skb[k].w, sm.u.f.ska[k])) {
                    sup = true;
                    break;
                }
            }
            if (!sup) {
                int p = atomicAdd(&g_nsurv, 1);
                g_skey[p] = ((ull)__float_as_uint(key) << 18) |
                            (ull)(0x3FFFFu - (unsigned)a);
            }
        }
    }
    grid_barrier(G, 5);

    // ================= Phase 6: serial tail (block0) =================
    if (bid == 0) {
        int nk3 = g_nk;
        int ns = g_nsurv;
        while (nk3 < MAXDET && ns > 0) {
            ull best = 0ULL;
            for (int i = t; i < ns; i += BLK) {
                ull v = g_skey[i];
                if (v > best) best = v;
            }
            sm.u.f.sb[t] = best;
            __syncthreads();
            for (int off = BLK / 2; off; off >>= 1) {
                if (t < off && sm.u.f.sb[t + off] > sm.u.f.sb[t])
                    sm.u.f.sb[t] = sm.u.f.sb[t + off];
                __syncthreads();
            }
            if (sm.u.f.sb[0] == 0ULL) break;

            if (t == 0) {
                int a = (int)(0x3FFFFu - (unsigned)(sm.u.f.sb[0] & 0x3FFFFULL));
                float4 b = g_boxes[a];
                float ar = g_areas[a];
                g_keep[nk3]  = a;
                g_kbox[nk3]  = b;
                g_karea[nk3] = ar;
                sm.u.f.swin = b;
                sm.u.f.swar = ar;
            }
            __syncthreads();
            float4 wb = sm.u.f.swin;
            float war = sm.u.f.swar;
            for (int i = t; i < ns; i += BLK) {
                ull v = g_skey[i];
                if (v != 0ULL) {
                    int a = (int)(0x3FFFFu - (unsigned)(v & 0x3FFFFULL));
                    float4 b = g_boxes[a];
                    if (sup_test(b.x, b.y, b.z, b.w, g_areas[a],
                                 wb.x, wb.y, wb.z, wb.w, war))
                        g_skey[i] = 0ULL;
                }
            }
            nk3++;
            __syncthreads();
        }
        __syncthreads();
        if (t == 0) g_nk = nk3;
    }
    grid_barrier(G, 6);

    // ================= Phase 7: final output =================
    nk = g_nk;
    int nwarp = (int)G * (BLK / 32);
    for (int d = bid * (BLK / 32) + wrp; d < MAXDET; d += nwarp) {
        bool valid = d < nk;
        float score = 0.f, clsid = -1.f;
        float bx0 = 0.f, bx1 = 0.f, bx2 = 0.f, bx3 = 0.f;
        if (valid) {
            int idx = g_keep[d];
            const float* row = cls + (size_t)idx * C;
            float best = -FLT_MAX;
            int bi = 0x7fffffff;
            for (int c = lane; c < C; c += 32) {
                float vv = row[c];
                if (vv > best) { best = vv; bi = c; }
            }
            #pragma unroll
            for (int off = 16; off; off >>= 1) {
                float ov = __shfl_down_sync(0xffffffffu, best, off);
                int   oi = __shfl_down_sync(0xffffffffu, bi,   off);
                if (ov > best || (ov == best && oi < bi)) { best = ov; bi = oi; }
            }
            best = __shfl_sync(0xffffffffu, best, 0);
            bi   = __shfl_sync(0xffffffffu, bi,   0);
            score = best;
            clsid = (float)bi;
            float4 b = g_kbox[d];
            bx0 = b.x; bx1 = b.y; bx2 = b.z; bx3 = b.w;
        }
        if (lane == 0) {
            out[d]                      = score;
            out[MAXDET + d]             = clsid;
            out[2 * MAXDET + 4 * d + 0] = bx0;
            out[2 * MAXDET + 4 * d + 1] = bx1;
            out[2 * MAXDET + 4 * d + 2] = bx2;
            out[2 * MAXDET + 4 * d + 3] = bx3;
            out[6 * MAXDET + d]         = valid ? 1.0f : 0.0f;
        }
    }

    // ---- exit protocol: last block resets barrier counters ----
    __syncthreads();
    if (t == 0) {
        unsigned v = atomicAdd(&g_done, 1u);
        if (v == G - 1u) {
            g_done = 0u;
            g_barcnt = 0u;
            __threadfence();
        }
    }
}

// ---------------------------------------------------------------------------
extern "C" void kernel_launch(void* const* d_in, const int* in_sizes, int n_in,
                              void* d_out, int out_size)
{
    const float* cls = (const float*)d_in[0];
    const float* reg = (const float*)d_in[1];
    const float* anc = (const float*)d_in[2];
    const int*   ph  = (n_in > 3) ? (const int*)d_in[3] : nullptr;
    const int*   pw  = (n_in > 4) ? (const int*)d_in[4] : nullptr;

    int A = in_sizes[2] / 4;
    if (A > MAXA) A = MAXA;
    int C = in_sizes[0] / A;

    static unsigned G = 0;
    if (G == 0) {
        int dev = 0;
        cudaGetDevice(&dev);
        cudaDeviceProp prop;
        cudaGetDeviceProperties(&prop, dev);
        int nb = 0;
        cudaOccupancyMaxActiveBlocksPerMultiprocessor(&nb, mega_kernel, BLK, 0);
        if (nb < 1) nb = 1;
        long long g = (long long)prop.multiProcessorCount * nb;
        if (g > 1024) g = 1024;
        if (g < 1) g = 1;
        G = (unsigned)g;
    }

    mega_kernel<<<G, BLK>>>(cls, reg, anc, ph, pw, A, C, (float*)d_out, G);
}